// round 10
// baseline (speedup 1.0000x reference)
#include <cuda_runtime.h>

#define N_QUBITS 7
#define DIM 128
#define DEPTH 2
#define NTHETA 14

typedef unsigned long long u64;

__device__ __forceinline__ u64 fma2(u64 a, u64 b, u64 c) {
    u64 d; asm("fma.rn.f32x2 %0, %1, %2, %3;" : "=l"(d) : "l"(a), "l"(b), "l"(c)); return d;
}
__device__ __forceinline__ u64 mul2(u64 a, u64 b) {
    u64 d; asm("mul.rn.f32x2 %0, %1, %2;" : "=l"(d) : "l"(a), "l"(b)); return d;
}
__device__ __forceinline__ u64 add2(u64 a, u64 b) {
    u64 d; asm("add.rn.f32x2 %0, %1, %2;" : "=l"(d) : "l"(a), "l"(b)); return d;
}
__device__ __forceinline__ u64 pack2(float lo, float hi) {
    u64 d; asm("mov.b64 %0, {%1, %2};" : "=l"(d) : "f"(lo), "f"(hi)); return d;
}

// Thread-per-row, one 32-row batch per warp, non-persistent (block churn gives
// cross-warp load/compute phase diversity; beats explicit pipelining and
// persistent grids — measured R5/R6).
//
// Coefficients t = tan(theta/2) are computed on lanes 0..13 AFTER the cp.async
// issue (hidden behind the DRAM fetch) and broadcast into every lane's
// REGISTERS via 14 shuffles. No smem/LDS in the hot loop (R9 lesson: smem
// coefficient loads cost ~4.5us of MIO latency chains vs register/LDC
// operands), no extra graph nodes (R5 lesson: prep kernel + memcpy = 5.2us).
//
// State: v[j] = (amp[2j], amp[2j+1]) packed f32x2, j = 0..63.
// Qubit q>=1 maps to bit (q-1) of j; qubit 0 is the lo/hi split.
// Tangent form: (A,B) -> (A - t*B, B + t*A); the global prod(cos) factor
// cancels in out = num / sum(probs).
__global__ void __launch_bounds__(64, 5)
qnat_main_kernel(const float* __restrict__ embed,
                 const float* __restrict__ theta,
                 float* __restrict__ out,
                 int nrows) {
    __shared__ ulonglong2 tile[2][32][32];   // [warp][row][16B chunk, XOR-swizzled]

    const int l = threadIdx.x & 31;
    const int w = threadIdx.x >> 5;

    const long long rowbase = ((long long)blockIdx.x * 2 + w) * 32;
    if (rowbase >= nrows) return;
    const int valid = (int)(((long long)nrows - rowbase) < 32 ? (nrows - rowbase) : 32);

    // ---- 1) issue the DRAM fetch first (coalesced cp.async, XOR-16B swizzle) ----
    const float4* src = reinterpret_cast<const float4*>(embed + rowbase * DIM);
    #pragma unroll
    for (int it = 0; it < 32; it++) {
        if (it < valid) {
            unsigned dst = (unsigned)__cvta_generic_to_shared(&tile[w][it][l ^ it]);
            asm volatile("cp.async.cg.shared.global [%0], [%1], 16;"
                         :: "r"(dst), "l"(src + it * 32 + l) : "memory");
        }
    }
    asm volatile("cp.async.commit_group;" ::: "memory");

    // ---- 2) coefficients -> registers, hidden behind the in-flight loads ----
    float tv = 0.0f;
    if (l < NTHETA) tv = __tanf(theta[l] * 0.5f);
    float tn[NTHETA];
    #pragma unroll
    for (int i = 0; i < NTHETA; i++)
        tn[i] = __shfl_sync(0xffffffffu, tv, i);

    // ---- 3) wait for data ----
    asm volatile("cp.async.wait_group 0;" ::: "memory");
    __syncwarp();
    if (l >= valid) return;

    // ---- own row into packed registers (conflict-free swizzled LDS.128) ----
    u64 v[64];
    #pragma unroll
    for (int i = 0; i < 32; i++) {
        ulonglong2 g = tile[w][l][i ^ l];
        v[2 * i]     = g.x;   // (amp 4i,   amp 4i+1)
        v[2 * i + 1] = g.y;   // (amp 4i+2, amp 4i+3)
    }

    // ---- 2 depths of 7 tangent-form RY rotations + CZ between ----
    #pragma unroll 1
    for (int d = 0; d < DEPTH; d++) {
        const int t0 = d * N_QUBITS;
        // qubit 0 (lo/hi split): v' = v + (-t,+t)*(hi,lo)
        {
            float t = tn[t0];
            u64 np = pack2(-t, t);
            #pragma unroll
            for (int j = 0; j < 64; j++) {
                u64 sw = (v[j] << 32) | (v[j] >> 32);
                v[j] = fma2(np, sw, v[j]);
            }
        }
        // qubits 1..6: A' = A - t*B ; B' = B + t*A
        #pragma unroll
        for (int q = 1; q < N_QUBITS; q++) {
            float t = tn[t0 + q];
            u64 tt = pack2(t, t);
            u64 nt = pack2(-t, -t);
            const int m = 1 << (q - 1);
            #pragma unroll
            for (int j = 0; j < 64; j++) {
                if (!(j & m)) {
                    u64 A = v[j];
                    v[j]     = fma2(nt, v[j + m], A);
                    v[j + m] = fma2(tt, A, v[j + m]);
                }
            }
        }
        // CZ after depth 0 only (final CZ erased by squaring): sign-bit masks
        if (d == 0) {
            #pragma unroll
            for (int j = 0; j < 64; j++) {
                int tb = j & (j >> 1);
                int pj = (tb ^ (tb >> 1) ^ (tb >> 2) ^ (tb >> 3) ^ (tb >> 4)) & 1;
                int ph = pj ^ (j & 1);
                u64 mask = (pj ? 0x80000000ull : 0ull) |
                           (ph ? 0x8000000000000000ull : 0ull);
                if (mask) v[j] ^= mask;
            }
        }
    }

    // ---- probabilities (packed squares) ----
    #pragma unroll
    for (int j = 0; j < 64; j++) v[j] = mul2(v[j], v[j]);

    // ---- in-place packed subset-sum tree over the 6 bits of j ----
    // invariant per block @base size 2^k: v[base]=total, v[base+2^t]=sum{bit_t=1}
    #pragma unroll
    for (int k = 0; k < 6; k++) {
        const int m = 1 << k;
        #pragma unroll
        for (int base = 0; base < 64; base += 2 * m) {
            v[base] = add2(v[base], v[base + m]);
            #pragma unroll
            for (int t = 0; t < k; t++)
                v[base + (1 << t)] = add2(v[base + (1 << t)], v[base + m + (1 << t)]);
        }
    }

    // ---- finalize: S, z0 from lo/hi split; z1..z6 from subset sums ----
    float lo = __uint_as_float((unsigned)v[0]);
    float hi = __uint_as_float((unsigned)(v[0] >> 32));
    float S   = lo + hi;
    float z0  = lo - hi;
    float inv = __fdividef(1.0f, S);

    float* o = out + (rowbase + l) * N_QUBITS;
    o[0] = z0 * inv;
    #pragma unroll
    for (int q = 1; q < N_QUBITS; q++) {
        u64 G = v[1 << (q - 1)];
        float gs = __uint_as_float((unsigned)G) + __uint_as_float((unsigned)(G >> 32));
        o[q] = fmaf(-2.0f * gs, inv, 1.0f);   // (S - 2*gs)/S
    }
}

extern "C" void kernel_launch(void* const* d_in, const int* in_sizes, int n_in,
                              void* d_out, int out_size) {
    const float* embed = (const float*)d_in[0];
    const float* theta = (const float*)d_in[1];
    float* out = (float*)d_out;

    int nrows = in_sizes[0] / DIM;
    int nwarps = (nrows + 31) / 32;
    int grid = (nwarps + 1) / 2;     // 2 warps (64 threads) per block

    qnat_main_kernel<<<grid, 64>>>(embed, theta, out, nrows);
}

// round 11
// speedup vs baseline: 1.2200x; 1.2200x over previous
#include <cuda_runtime.h>

#define N_QUBITS 7
#define DIM 128
#define DEPTH 2
#define NTHETA 14

typedef unsigned long long u64;

__device__ __forceinline__ u64 fma2(u64 a, u64 b, u64 c) {
    u64 d; asm("fma.rn.f32x2 %0, %1, %2, %3;" : "=l"(d) : "l"(a), "l"(b), "l"(c)); return d;
}
__device__ __forceinline__ u64 mul2(u64 a, u64 b) {
    u64 d; asm("mul.rn.f32x2 %0, %1, %2;" : "=l"(d) : "l"(a), "l"(b)); return d;
}
__device__ __forceinline__ u64 add2(u64 a, u64 b) {
    u64 d; asm("add.rn.f32x2 %0, %1, %2;" : "=l"(d) : "l"(a), "l"(b)); return d;
}
__device__ __forceinline__ u64 pack2(float lo, float hi) {
    u64 d; asm("mov.b64 %0, {%1, %2};" : "=l"(d) : "f"(lo), "f"(hi)); return d;
}

// Thread-per-row, one 32-row batch per warp, non-persistent (block churn gives
// cross-warp load/compute phase diversity; beats explicit pipelining and
// persistent grids — measured R5/R6).
//
// Coefficients t = tan(theta/2): computed on lanes 0..13 AFTER the cp.async
// issue (hidden behind the DRAM fetch), broadcast into registers via 14
// shuffles. The DEPTH loop is FULLY UNROLLED so tn[] is indexed only by
// compile-time constants and stays register-resident (R10 lesson: with
// "#pragma unroll 1" the index d*7+q is dynamic -> tn[] demoted to local
// memory -> LDL chains in every qubit stage; the R5/R8/R10 perf ladder is
// exactly LDC < LDS < LDL access cost).
//
// State: v[j] = (amp[2j], amp[2j+1]) packed f32x2, j = 0..63.
// Qubit q>=1 maps to bit (q-1) of j; qubit 0 is the lo/hi split.
// Tangent form: (A,B) -> (A - t*B, B + t*A); the global prod(cos) factor
// cancels in out = num / sum(probs).
__global__ void __launch_bounds__(64, 5)
qnat_main_kernel(const float* __restrict__ embed,
                 const float* __restrict__ theta,
                 float* __restrict__ out,
                 int nrows) {
    __shared__ ulonglong2 tile[2][32][32];   // [warp][row][16B chunk, XOR-swizzled]

    const int l = threadIdx.x & 31;
    const int w = threadIdx.x >> 5;

    const long long rowbase = ((long long)blockIdx.x * 2 + w) * 32;
    if (rowbase >= nrows) return;
    const int valid = (int)(((long long)nrows - rowbase) < 32 ? (nrows - rowbase) : 32);

    // ---- 1) issue the DRAM fetch first (coalesced cp.async, XOR-16B swizzle) ----
    const float4* src = reinterpret_cast<const float4*>(embed + rowbase * DIM);
    #pragma unroll
    for (int it = 0; it < 32; it++) {
        if (it < valid) {
            unsigned dst = (unsigned)__cvta_generic_to_shared(&tile[w][it][l ^ it]);
            asm volatile("cp.async.cg.shared.global [%0], [%1], 16;"
                         :: "r"(dst), "l"(src + it * 32 + l) : "memory");
        }
    }
    asm volatile("cp.async.commit_group;" ::: "memory");

    // ---- 2) coefficients -> registers, hidden behind the in-flight loads ----
    float tv = 0.0f;
    if (l < NTHETA) tv = __tanf(theta[l] * 0.5f);
    float tn[NTHETA];
    #pragma unroll
    for (int i = 0; i < NTHETA; i++)
        tn[i] = __shfl_sync(0xffffffffu, tv, i);

    // ---- 3) wait for data ----
    asm volatile("cp.async.wait_group 0;" ::: "memory");
    __syncwarp();
    if (l >= valid) return;

    // ---- own row into packed registers (conflict-free swizzled LDS.128) ----
    u64 v[64];
    #pragma unroll
    for (int i = 0; i < 32; i++) {
        ulonglong2 g = tile[w][l][i ^ l];
        v[2 * i]     = g.x;   // (amp 4i,   amp 4i+1)
        v[2 * i + 1] = g.y;   // (amp 4i+2, amp 4i+3)
    }

    // ---- 2 depths of 7 tangent-form RY rotations + CZ between ----
    // FULLY unrolled: all tn[] indices are compile-time constants.
    #pragma unroll
    for (int d = 0; d < DEPTH; d++) {
        const int t0 = d * N_QUBITS;
        // qubit 0 (lo/hi split): v' = v + (-t,+t)*(hi,lo)
        {
            float t = tn[t0];
            u64 np = pack2(-t, t);
            #pragma unroll
            for (int j = 0; j < 64; j++) {
                u64 sw = (v[j] << 32) | (v[j] >> 32);
                v[j] = fma2(np, sw, v[j]);
            }
        }
        // qubits 1..6: A' = A - t*B ; B' = B + t*A
        #pragma unroll
        for (int q = 1; q < N_QUBITS; q++) {
            float t = tn[t0 + q];
            u64 tt = pack2(t, t);
            u64 nt = pack2(-t, -t);
            const int m = 1 << (q - 1);
            #pragma unroll
            for (int j = 0; j < 64; j++) {
                if (!(j & m)) {
                    u64 A = v[j];
                    v[j]     = fma2(nt, v[j + m], A);
                    v[j + m] = fma2(tt, A, v[j + m]);
                }
            }
        }
        // CZ after depth 0 only (final CZ erased by squaring): sign-bit masks
        if (d == 0) {
            #pragma unroll
            for (int j = 0; j < 64; j++) {
                int tb = j & (j >> 1);
                int pj = (tb ^ (tb >> 1) ^ (tb >> 2) ^ (tb >> 3) ^ (tb >> 4)) & 1;
                int ph = pj ^ (j & 1);
                u64 mask = (pj ? 0x80000000ull : 0ull) |
                           (ph ? 0x8000000000000000ull : 0ull);
                if (mask) v[j] ^= mask;
            }
        }
    }

    // ---- probabilities (packed squares) ----
    #pragma unroll
    for (int j = 0; j < 64; j++) v[j] = mul2(v[j], v[j]);

    // ---- in-place packed subset-sum tree over the 6 bits of j ----
    // invariant per block @base size 2^k: v[base]=total, v[base+2^t]=sum{bit_t=1}
    #pragma unroll
    for (int k = 0; k < 6; k++) {
        const int m = 1 << k;
        #pragma unroll
        for (int base = 0; base < 64; base += 2 * m) {
            v[base] = add2(v[base], v[base + m]);
            #pragma unroll
            for (int t = 0; t < k; t++)
                v[base + (1 << t)] = add2(v[base + (1 << t)], v[base + m + (1 << t)]);
        }
    }

    // ---- finalize: S, z0 from lo/hi split; z1..z6 from subset sums ----
    float lo = __uint_as_float((unsigned)v[0]);
    float hi = __uint_as_float((unsigned)(v[0] >> 32));
    float S   = lo + hi;
    float z0  = lo - hi;
    float inv = __fdividef(1.0f, S);

    float* o = out + (rowbase + l) * N_QUBITS;
    o[0] = z0 * inv;
    #pragma unroll
    for (int q = 1; q < N_QUBITS; q++) {
        u64 G = v[1 << (q - 1)];
        float gs = __uint_as_float((unsigned)G) + __uint_as_float((unsigned)(G >> 32));
        o[q] = fmaf(-2.0f * gs, inv, 1.0f);   // (S - 2*gs)/S
    }
}

extern "C" void kernel_launch(void* const* d_in, const int* in_sizes, int n_in,
                              void* d_out, int out_size) {
    const float* embed = (const float*)d_in[0];
    const float* theta = (const float*)d_in[1];
    float* out = (float*)d_out;

    int nrows = in_sizes[0] / DIM;
    int nwarps = (nrows + 31) / 32;
    int grid = (nwarps + 1) / 2;     // 2 warps (64 threads) per block

    qnat_main_kernel<<<grid, 64>>>(embed, theta, out, nrows);
}